// round 1
// baseline (speedup 1.0000x reference)
#include <cuda_runtime.h>
#include <math.h>

// Problem constants (fixed by the dataset): B=32, Cin=Cout=64, N=8192, modes=32
#define N_T    8192
#define N_ROWS 2048          // B * C
#define N_F    32
#define N_J    64            // 2 * N_F (interleaved re/im columns)
#define SPLITK 32
#define KCHUNK (N_T / SPLITK)   // 256

// ---------------- device scratch (no allocations allowed) ----------------
__device__ float  g_tab_fwd[N_T * N_J];            // [t][j]: j=2f -> cos, j=2f+1 -> -sin   (2 MB)
__device__ float  g_tab_inv[N_J * N_T];            // [j][t]: j=2f -> cos, j=2f+1 -> sin    (2 MB)
__device__ float2 g_cftA[160 * N_F];               // combined CFT weights (Ar, Ai)
__device__ int    g_cft_left[160];
__device__ int    g_cft_right[160];
__device__ float  g_cft_wl[160];
__device__ float  g_cft_wr[160];
__device__ float  g_Xpart[SPLITK * N_ROWS * N_J];  // split-K partials (16 MB)
__device__ float  g_Xc[N_ROWS * N_J];              // rfft modes, interleaved re/im
__device__ float  g_gnorm[N_ROWS * N_F];           // layernormed CFT magnitude
__device__ float  g_Gc[N_ROWS * N_J];              // gated+mixed modes, scaled for irfft

// ---------------- setup: trig tables (deterministic, cheap) ----------------
__global__ void k_setup_tables() {
  int idx = blockIdx.x * blockDim.x + threadIdx.x;
  if (idx >= N_T * N_J) return;
  int t = idx >> 6, j = idx & 63, f = j >> 1;
  int r = (f * t) & (N_T - 1);                  // exact integer phase mod N
  float s, c;
  sincospif((float)r * (1.0f / 4096.0f), &s, &c);  // theta = 2*pi*r/8192 = pi*(r/4096)
  g_tab_fwd[t * N_J + j] = (j & 1) ? -s : c;
  g_tab_inv[j * N_T + t] = (j & 1) ?  s : c;
}

// ---------------- setup: CFT combined weights + interpolation constants ----------------
// Faithful to the reference (including its k/m einsum index aliasing and f32 searchsorted).
__global__ void k_setup_cft() {
  const double PI = 3.14159265358979323846;
  int tid = threadIdx.x;
  if (tid < 160) {
    int l = tid >> 3, m = tid & 7;
    double cheb = -cos((2.0 * m + 1.0) * PI / 16.0);
    double tseg = (double)l / 20.0 + 0.025 * (cheb + 1.0);
    float ts = (float)tseg;
    // searchsorted(linspace(0,1,8192), ts, side='left') with t[i] = i/8191 in f32
    int right = (int)ceilf(ts * 8191.0f);
    if (right < 1) right = 1;
    while (right > 0 && (float)(right - 1) / 8191.0f >= ts) right--;
    while (right < 8191 && (float)right / 8191.0f < ts) right++;
    if (right > 8191) right = 8191;
    int left = right - 1; if (left < 0) left = 0;
    float tl = (float)left / 8191.0f;
    float tr = (float)right / 8191.0f;
    float den = (tr - tl == 0.0f) ? 1.0f : (tr - tl);
    float wr = (ts - tl) / den;
    g_cft_left[tid] = left;
    g_cft_right[tid] = right;
    g_cft_wr[tid] = wr;
    g_cft_wl[tid] = 1.0f - wr;
  }
  for (int e = tid; e < 160 * 32; e += blockDim.x) {
    int p = e >> 5, f = e & 31;
    int l = p >> 3, kk = p & 7;   // kk plays the "k" role (reference aliases k with node m)
    double Wr = 0.0, Wi = 0.0;
    for (int mm = 0; mm < 8; mm++) {
      double cheb = -cos((2.0 * mm + 1.0) * PI / 16.0);
      double T   = cos((double)kk * acos(cheb));
      double ang = cheb * (double)f * PI * 0.05;   // cheb * f * pi * seg_len
      Wr += T * cos(ang);
      Wi -= T * sin(ang);
    }
    Wr *= 0.025; Wi *= 0.025;                      // * seg_len/2
    double phi = 2.0 * PI * ((double)l / 20.0) * (double)f;
    double cs = cos(phi), sn = sin(phi);
    g_cftA[e] = make_float2((float)( Wr * cs + Wi * sn),
                            (float)(-Wr * sn + Wi * cs));
  }
}

// ---------------- kernel A: forward pruned DFT as SGEMM with split-K ----------------
// Xpart[split][m][j] = sum_{k in chunk} x[m][k] * tab_fwd[k][j]
__global__ __launch_bounds__(256) void k_fwd_dft(const float* __restrict__ x) {
  __shared__ float As[16][132];   // transposed x tile [k][m], padded
  __shared__ float Bs[16][64];    // tab tile [k][j]
  const int tid = threadIdx.x;
  const int tx = tid & 15, ty = tid >> 4;
  const int m0 = blockIdx.x * 128;
  const int k0 = blockIdx.y * KCHUNK;
  const int lrow = tid >> 2, lkq = tid & 3;   // A loader: 64 rows x 4 float4-cols (x2 rows)
  const int bkr  = tid >> 4, bcq = tid & 15;  // B loader: 16 rows x 16 float4-cols

  float acc[8][4];
#pragma unroll
  for (int i = 0; i < 8; i++)
#pragma unroll
    for (int j = 0; j < 4; j++) acc[i][j] = 0.0f;

  for (int kt = 0; kt < KCHUNK; kt += 16) {
    float4 a0 = *(const float4*)(x + (size_t)(m0 + lrow)      * N_T + k0 + kt + lkq * 4);
    float4 a1 = *(const float4*)(x + (size_t)(m0 + lrow + 64) * N_T + k0 + kt + lkq * 4);
    float4 b0 = *(const float4*)(g_tab_fwd + (size_t)(k0 + kt + bkr) * N_J + bcq * 4);
    __syncthreads();
    As[lkq * 4 + 0][lrow] = a0.x; As[lkq * 4 + 1][lrow] = a0.y;
    As[lkq * 4 + 2][lrow] = a0.z; As[lkq * 4 + 3][lrow] = a0.w;
    As[lkq * 4 + 0][lrow + 64] = a1.x; As[lkq * 4 + 1][lrow + 64] = a1.y;
    As[lkq * 4 + 2][lrow + 64] = a1.z; As[lkq * 4 + 3][lrow + 64] = a1.w;
    *(float4*)&Bs[bkr][bcq * 4] = b0;
    __syncthreads();
#pragma unroll
    for (int k = 0; k < 16; k++) {
      float4 av0 = *(const float4*)&As[k][ty * 8];
      float4 av1 = *(const float4*)&As[k][ty * 8 + 4];
      float4 bv  = *(const float4*)&Bs[k][tx * 4];
      float ar[8] = {av0.x, av0.y, av0.z, av0.w, av1.x, av1.y, av1.z, av1.w};
      float br[4] = {bv.x, bv.y, bv.z, bv.w};
#pragma unroll
      for (int i = 0; i < 8; i++)
#pragma unroll
        for (int j = 0; j < 4; j++) acc[i][j] += ar[i] * br[j];
    }
  }
  float* outp = g_Xpart + ((size_t)blockIdx.y * N_ROWS + m0) * N_J;
#pragma unroll
  for (int i = 0; i < 8; i++) {
    *(float4*)(outp + (size_t)(ty * 8 + i) * N_J + tx * 4) =
        make_float4(acc[i][0], acc[i][1], acc[i][2], acc[i][3]);
  }
}

// ---------------- split-K reduction (fixed order -> deterministic) ----------------
__global__ void k_reduce_x() {
  int e = blockIdx.x * blockDim.x + threadIdx.x;
  if (e >= N_ROWS * N_J) return;
  float s = 0.0f;
#pragma unroll
  for (int i = 0; i < SPLITK; i++) s += g_Xpart[(size_t)i * N_ROWS * N_J + e];
  g_Xc[e] = s;
}

// ---------------- kernel B: CFT magnitude + LayerNorm (one warp per row) ----------------
__global__ __launch_bounds__(256) void k_cft_norm(const float* __restrict__ x,
                                                  const float* __restrict__ gamma,
                                                  const float* __restrict__ beta) {
  __shared__ float seg[8][160];
  int w = threadIdx.x >> 5, lane = threadIdx.x & 31;
  int m = blockIdx.x * 8 + w;
  const float* xr = x + (size_t)m * N_T;
  for (int p = lane; p < 160; p += 32)
    seg[w][p] = g_cft_wl[p] * xr[g_cft_left[p]] + g_cft_wr[p] * xr[g_cft_right[p]];
  __syncwarp();
  float re = 0.0f, im = 0.0f;
#pragma unroll 8
  for (int p = 0; p < 160; p++) {
    float s = seg[w][p];
    float2 A = g_cftA[p * 32 + lane];
    re += s * A.x;
    im += s * A.y;
  }
  float mag = sqrtf(re * re + im * im);
  float mu = mag;
#pragma unroll
  for (int o = 16; o; o >>= 1) mu += __shfl_xor_sync(0xffffffffu, mu, o);
  mu *= (1.0f / 32.0f);
  float d = mag - mu;
  float v = d * d;
#pragma unroll
  for (int o = 16; o; o >>= 1) v += __shfl_xor_sync(0xffffffffu, v, o);
  v *= (1.0f / 32.0f);
  float g = d / sqrtf(v + 1e-5f) * gamma[lane] + beta[lane];
  g_gnorm[m * 32 + lane] = g;
}

// ---------------- kernel C: sigmoid gate + per-mode complex channel mix ----------------
__global__ __launch_bounds__(256) void k_gate_mix(const float* __restrict__ w1r,
                                                  const float* __restrict__ w1i,
                                                  const float* __restrict__ gw) {
  __shared__ float sgn[64 * 32];
  __shared__ float sgw[64 * 64];
  __shared__ float sgr[64 * 32];
  __shared__ float sgi[64 * 32];
  int b = blockIdx.x, tid = threadIdx.x;
  for (int e = tid; e < 64 * 32; e += 256) sgn[e] = g_gnorm[b * 2048 + e];
  for (int e = tid; e < 64 * 64; e += 256) sgw[e] = gw[e];
  __syncthreads();
  for (int e = tid; e < 64 * 32; e += 256) {
    int o = e >> 5, f = e & 31;
    float s = 0.0f;
#pragma unroll 8
    for (int i = 0; i < 64; i++) s += sgw[o * 64 + i] * sgn[i * 32 + f];
    float gate = 1.0f / (1.0f + expf(-s));
    float xrv = g_Xc[(b * 64 + o) * 64 + 2 * f];
    float xiv = g_Xc[(b * 64 + o) * 64 + 2 * f + 1];
    sgr[e] = xrv * gate;      // e == o*32 + f; channel index shared (Cin == Cout)
    sgi[e] = xiv * gate;
  }
  __syncthreads();
  for (int e = tid; e < 64 * 32; e += 256) {
    int o = e >> 5, f = e & 31;
    float ar = 0.0f, ai = 0.0f;
#pragma unroll 4
    for (int i = 0; i < 64; i++) {
      float wr = w1r[i * 2048 + o * 32 + f];
      float wi = w1i[i * 2048 + o * 32 + f];
      float gr = sgr[i * 32 + f];
      float gi = sgi[i * 32 + f];
      ar += gr * wr - gi * wi;
      ai += gr * wi + gi * wr;
    }
    // fold irfft constants: 1/n, x2 for f>=1, and the -Gi sign for the sin row
    float alpha = (f == 0 ? 1.0f : 2.0f) * (1.0f / 8192.0f);
    g_Gc[(b * 64 + o) * 64 + 2 * f]     =  alpha * ar;
    g_Gc[(b * 64 + o) * 64 + 2 * f + 1] = -alpha * ai;
  }
}

// ---------------- kernel D: inverse pruned DFT as SGEMM (K=64 resident) ----------------
__global__ __launch_bounds__(256) void k_inv_dft(float* __restrict__ out) {
  __shared__ float As[64][64];    // Gc tile [m][j]
  __shared__ float Bs[64][128];   // tab_inv tile [j][t]
  const int tid = threadIdx.x;
  const int tx = tid & 15, ty = tid >> 4;
  const int t0 = blockIdx.x * 128;
  const int m0 = blockIdx.y * 64;
#pragma unroll
  for (int u = 0; u < 4; u++) {
    int idx = tid + u * 256;
    int r = idx >> 4, c4 = idx & 15;
    *(float4*)&As[r][c4 * 4] = *(const float4*)(g_Gc + (size_t)(m0 + r) * N_J + c4 * 4);
  }
#pragma unroll
  for (int u = 0; u < 8; u++) {
    int idx = tid + u * 256;
    int r = idx >> 5, c4 = idx & 31;
    *(float4*)&Bs[r][c4 * 4] = *(const float4*)(g_tab_inv + (size_t)r * N_T + t0 + c4 * 4);
  }
  __syncthreads();
  float acc[4][8];
#pragma unroll
  for (int i = 0; i < 4; i++)
#pragma unroll
    for (int j = 0; j < 8; j++) acc[i][j] = 0.0f;
#pragma unroll 8
  for (int k = 0; k < 64; k++) {
    float ar[4] = {As[ty * 4 + 0][k], As[ty * 4 + 1][k],
                   As[ty * 4 + 2][k], As[ty * 4 + 3][k]};
    float4 b0 = *(const float4*)&Bs[k][tx * 4];
    float4 b1 = *(const float4*)&Bs[k][tx * 4 + 64];
    float br[8] = {b0.x, b0.y, b0.z, b0.w, b1.x, b1.y, b1.z, b1.w};
#pragma unroll
    for (int i = 0; i < 4; i++)
#pragma unroll
      for (int j = 0; j < 8; j++) acc[i][j] += ar[i] * br[j];
  }
#pragma unroll
  for (int i = 0; i < 4; i++) {
    float* op = out + (size_t)(m0 + ty * 4 + i) * N_T + t0;
    *(float4*)(op + tx * 4)      = make_float4(acc[i][0], acc[i][1], acc[i][2], acc[i][3]);
    *(float4*)(op + tx * 4 + 64) = make_float4(acc[i][4], acc[i][5], acc[i][6], acc[i][7]);
  }
}

// ---------------- launch ----------------
extern "C" void kernel_launch(void* const* d_in, const int* in_sizes, int n_in,
                              void* d_out, int out_size) {
  const float* x     = (const float*)d_in[0];   // (32, 64, 8192)
  const float* w1r   = (const float*)d_in[1];   // (64, 64, 32)
  const float* w1i   = (const float*)d_in[2];   // (64, 64, 32)
  const float* gw    = (const float*)d_in[3];   // (64, 64)
  const float* gamma = (const float*)d_in[4];   // (32,)
  const float* beta  = (const float*)d_in[5];   // (32,)
  float* out = (float*)d_out;                   // (32, 64, 8192)

  k_setup_tables<<<(N_T * N_J + 255) / 256, 256>>>();
  k_setup_cft<<<1, 256>>>();
  k_fwd_dft<<<dim3(N_ROWS / 128, SPLITK), 256>>>(x);
  k_reduce_x<<<(N_ROWS * N_J + 255) / 256, 256>>>();
  k_cft_norm<<<N_ROWS / 8, 256>>>(x, gamma, beta);
  k_gate_mix<<<32, 256>>>(w1r, w1i, gw);
  k_inv_dft<<<dim3(N_T / 128, N_ROWS / 64), 256>>>(out);
}

// round 5
// speedup vs baseline: 6.7918x; 6.7918x over previous
#include <cuda_runtime.h>
#include <math.h>

// Problem constants (fixed by the dataset): B=32, Cin=Cout=64, N=8192, modes=32
#define N_T    8192
#define N_ROWS 2048          // B * C
#define N_F    32
#define N_J    64            // 2 * N_F (interleaved re/im columns)
#define SPLITK 32
#define KCHUNK (N_T / SPLITK)   // 256

// ---------------- device scratch (no allocations allowed) ----------------
__device__ float  g_tab_fwd[N_T * N_J];            // [t][j]: j=2f -> cos, j=2f+1 -> -sin   (2 MB)
__device__ float  g_tab_inv[N_J * N_T];            // [j][t]: j=2f -> cos, j=2f+1 -> sin    (2 MB)
__device__ float2 g_cftA[160 * N_F];               // combined CFT weights (Ar, Ai)
__device__ int    g_cft_left[160];
__device__ int    g_cft_right[160];
__device__ float  g_cft_wl[160];
__device__ float  g_cft_wr[160];
__device__ float  g_Xpart[SPLITK * N_ROWS * N_J];  // split-K partials (16 MB)
__device__ float  g_Xc[N_ROWS * N_J];              // rfft modes, interleaved re/im
__device__ float  g_gnorm[N_ROWS * N_F];           // layernormed CFT magnitude
__device__ float  g_Gc[N_ROWS * N_J];              // gated+mixed modes, scaled for irfft

// ---------------- setup: trig tables (deterministic, cheap) ----------------
__global__ void k_setup_tables() {
  int idx = blockIdx.x * blockDim.x + threadIdx.x;
  if (idx >= N_T * N_J) return;
  int t = idx >> 6, j = idx & 63, f = j >> 1;
  int r = (f * t) & (N_T - 1);                  // exact integer phase mod N
  float s, c;
  sincospif((float)r * (1.0f / 4096.0f), &s, &c);  // theta = 2*pi*r/8192 = pi*(r/4096)
  g_tab_fwd[t * N_J + j] = (j & 1) ? -s : c;
  g_tab_inv[j * N_T + t] = (j & 1) ?  s : c;
}

// ---------------- setup: CFT combined weights + interpolation constants ----------------
// All angles are rational multiples of pi -> use sincospif/cospif in fp32.
// fp32 matches the reference's own precision (JAX default float32).
// One entry per thread, 20 blocks x 256 threads.
__global__ void k_setup_cft() {
  int e = blockIdx.x * blockDim.x + threadIdx.x;
  if (e < 160) {
    int l = e >> 3, m = e & 7;
    float cheb = -cospif((2.0f * m + 1.0f) / 16.0f);
    float ts = (float)l / 20.0f + 0.025f * (cheb + 1.0f);
    // searchsorted(linspace(0,1,8192), ts, side='left') with t[i] = i/8191 in f32
    int right = (int)ceilf(ts * 8191.0f);
    if (right < 1) right = 1;
    while (right > 0 && (float)(right - 1) / 8191.0f >= ts) right--;
    while (right < 8191 && (float)right / 8191.0f < ts) right++;
    if (right > 8191) right = 8191;
    int left = right - 1; if (left < 0) left = 0;
    float tl = (float)left / 8191.0f;
    float tr = (float)right / 8191.0f;
    float den = (tr - tl == 0.0f) ? 1.0f : (tr - tl);
    float wr = (ts - tl) / den;
    g_cft_left[e] = left;
    g_cft_right[e] = right;
    g_cft_wr[e] = wr;
    g_cft_wl[e] = 1.0f - wr;
  }
  if (e >= 160 * 32) return;
  int p = e >> 5, f = e & 31;
  int l = p >> 3, kk = p & 7;   // kk plays the "k" role (reference aliases k with node m)
  float Wr = 0.0f, Wi = 0.0f;
#pragma unroll
  for (int mm = 0; mm < 8; mm++) {
    float q = (2.0f * mm + 1.0f) / 16.0f;
    float cheb = -cospif(q);                 // node in [-1,1]
    float T = cospif((float)kk * (1.0f - q)); // cos(kk * acos(cheb)), acos(cheb)=pi*(1-q)
    float s, c;
    sincospif(cheb * (float)f * 0.05f, &s, &c);  // ang = cheb * f * pi * seg_len
    Wr += T * c;
    Wi -= T * s;
  }
  Wr *= 0.025f; Wi *= 0.025f;                // * seg_len/2
  // phi = 2*pi*(l/20)*f  ->  phi/pi = l*f/10, reduce mod 2 via (l*f) mod 20
  float qphi = (float)((l * f) % 20) * 0.1f;
  float sn, cs;
  sincospif(qphi, &sn, &cs);
  g_cftA[e] = make_float2( Wr * cs + Wi * sn,
                          -Wr * sn + Wi * cs);
}

// ---------------- kernel A: forward pruned DFT as SGEMM with split-K ----------------
// Xpart[split][m][j] = sum_{k in chunk} x[m][k] * tab_fwd[k][j]
__global__ __launch_bounds__(256) void k_fwd_dft(const float* __restrict__ x) {
  __shared__ float As[16][132];   // transposed x tile [k][m], padded
  __shared__ float Bs[16][64];    // tab tile [k][j]
  const int tid = threadIdx.x;
  const int tx = tid & 15, ty = tid >> 4;
  const int m0 = blockIdx.x * 128;
  const int k0 = blockIdx.y * KCHUNK;
  const int lrow = tid >> 2, lkq = tid & 3;   // A loader: 64 rows x 4 float4-cols (x2 rows)
  const int bkr  = tid >> 4, bcq = tid & 15;  // B loader: 16 rows x 16 float4-cols

  float acc[8][4];
#pragma unroll
  for (int i = 0; i < 8; i++)
#pragma unroll
    for (int j = 0; j < 4; j++) acc[i][j] = 0.0f;

  for (int kt = 0; kt < KCHUNK; kt += 16) {
    float4 a0 = *(const float4*)(x + (size_t)(m0 + lrow)      * N_T + k0 + kt + lkq * 4);
    float4 a1 = *(const float4*)(x + (size_t)(m0 + lrow + 64) * N_T + k0 + kt + lkq * 4);
    float4 b0 = *(const float4*)(g_tab_fwd + (size_t)(k0 + kt + bkr) * N_J + bcq * 4);
    __syncthreads();
    As[lkq * 4 + 0][lrow] = a0.x; As[lkq * 4 + 1][lrow] = a0.y;
    As[lkq * 4 + 2][lrow] = a0.z; As[lkq * 4 + 3][lrow] = a0.w;
    As[lkq * 4 + 0][lrow + 64] = a1.x; As[lkq * 4 + 1][lrow + 64] = a1.y;
    As[lkq * 4 + 2][lrow + 64] = a1.z; As[lkq * 4 + 3][lrow + 64] = a1.w;
    *(float4*)&Bs[bkr][bcq * 4] = b0;
    __syncthreads();
#pragma unroll
    for (int k = 0; k < 16; k++) {
      float4 av0 = *(const float4*)&As[k][ty * 8];
      float4 av1 = *(const float4*)&As[k][ty * 8 + 4];
      float4 bv  = *(const float4*)&Bs[k][tx * 4];
      float ar[8] = {av0.x, av0.y, av0.z, av0.w, av1.x, av1.y, av1.z, av1.w};
      float br[4] = {bv.x, bv.y, bv.z, bv.w};
#pragma unroll
      for (int i = 0; i < 8; i++)
#pragma unroll
        for (int j = 0; j < 4; j++) acc[i][j] += ar[i] * br[j];
    }
  }
  float* outp = g_Xpart + ((size_t)blockIdx.y * N_ROWS + m0) * N_J;
#pragma unroll
  for (int i = 0; i < 8; i++) {
    *(float4*)(outp + (size_t)(ty * 8 + i) * N_J + tx * 4) =
        make_float4(acc[i][0], acc[i][1], acc[i][2], acc[i][3]);
  }
}

// ---------------- split-K reduction (fixed order -> deterministic) ----------------
__global__ void k_reduce_x() {
  int e = blockIdx.x * blockDim.x + threadIdx.x;
  if (e >= N_ROWS * N_J) return;
  float s = 0.0f;
#pragma unroll
  for (int i = 0; i < SPLITK; i++) s += g_Xpart[(size_t)i * N_ROWS * N_J + e];
  g_Xc[e] = s;
}

// ---------------- kernel B: CFT magnitude + LayerNorm (one warp per row) ----------------
__global__ __launch_bounds__(256) void k_cft_norm(const float* __restrict__ x,
                                                  const float* __restrict__ gamma,
                                                  const float* __restrict__ beta) {
  __shared__ float seg[8][160];
  int w = threadIdx.x >> 5, lane = threadIdx.x & 31;
  int m = blockIdx.x * 8 + w;
  const float* xr = x + (size_t)m * N_T;
  for (int p = lane; p < 160; p += 32)
    seg[w][p] = g_cft_wl[p] * xr[g_cft_left[p]] + g_cft_wr[p] * xr[g_cft_right[p]];
  __syncwarp();
  float re = 0.0f, im = 0.0f;
#pragma unroll 8
  for (int p = 0; p < 160; p++) {
    float s = seg[w][p];
    float2 A = g_cftA[p * 32 + lane];
    re += s * A.x;
    im += s * A.y;
  }
  float mag = sqrtf(re * re + im * im);
  float mu = mag;
#pragma unroll
  for (int o = 16; o; o >>= 1) mu += __shfl_xor_sync(0xffffffffu, mu, o);
  mu *= (1.0f / 32.0f);
  float d = mag - mu;
  float v = d * d;
#pragma unroll
  for (int o = 16; o; o >>= 1) v += __shfl_xor_sync(0xffffffffu, v, o);
  v *= (1.0f / 32.0f);
  float g = d / sqrtf(v + 1e-5f) * gamma[lane] + beta[lane];
  g_gnorm[m * 32 + lane] = g;
}

// ---------------- kernel C: sigmoid gate + per-mode complex channel mix ----------------
__global__ __launch_bounds__(256) void k_gate_mix(const float* __restrict__ w1r,
                                                  const float* __restrict__ w1i,
                                                  const float* __restrict__ gw) {
  __shared__ float sgn[64 * 32];
  __shared__ float sgw[64 * 64];
  __shared__ float sgr[64 * 32];
  __shared__ float sgi[64 * 32];
  int b = blockIdx.x, tid = threadIdx.x;
  for (int e = tid; e < 64 * 32; e += 256) sgn[e] = g_gnorm[b * 2048 + e];
  for (int e = tid; e < 64 * 64; e += 256) sgw[e] = gw[e];
  __syncthreads();
  for (int e = tid; e < 64 * 32; e += 256) {
    int o = e >> 5, f = e & 31;
    float s = 0.0f;
#pragma unroll 8
    for (int i = 0; i < 64; i++) s += sgw[o * 64 + i] * sgn[i * 32 + f];
    float gate = 1.0f / (1.0f + expf(-s));
    float xrv = g_Xc[(b * 64 + o) * 64 + 2 * f];
    float xiv = g_Xc[(b * 64 + o) * 64 + 2 * f + 1];
    sgr[e] = xrv * gate;      // e == o*32 + f; channel index shared (Cin == Cout)
    sgi[e] = xiv * gate;
  }
  __syncthreads();
  for (int e = tid; e < 64 * 32; e += 256) {
    int o = e >> 5, f = e & 31;
    float ar = 0.0f, ai = 0.0f;
#pragma unroll 4
    for (int i = 0; i < 64; i++) {
      float wr = w1r[i * 2048 + o * 32 + f];
      float wi = w1i[i * 2048 + o * 32 + f];
      float gr = sgr[i * 32 + f];
      float gi = sgi[i * 32 + f];
      ar += gr * wr - gi * wi;
      ai += gr * wi + gi * wr;
    }
    // fold irfft constants: 1/n, x2 for f>=1, and the -Gi sign for the sin row
    float alpha = (f == 0 ? 1.0f : 2.0f) * (1.0f / 8192.0f);
    g_Gc[(b * 64 + o) * 64 + 2 * f]     =  alpha * ar;
    g_Gc[(b * 64 + o) * 64 + 2 * f + 1] = -alpha * ai;
  }
}

// ---------------- kernel D: inverse pruned DFT as SGEMM (K=64 resident) ----------------
__global__ __launch_bounds__(256) void k_inv_dft(float* __restrict__ out) {
  __shared__ float As[64][64];    // Gc tile [m][j]
  __shared__ float Bs[64][128];   // tab_inv tile [j][t]
  const int tid = threadIdx.x;
  const int tx = tid & 15, ty = tid >> 4;
  const int t0 = blockIdx.x * 128;
  const int m0 = blockIdx.y * 64;
#pragma unroll
  for (int u = 0; u < 4; u++) {
    int idx = tid + u * 256;
    int r = idx >> 4, c4 = idx & 15;
    *(float4*)&As[r][c4 * 4] = *(const float4*)(g_Gc + (size_t)(m0 + r) * N_J + c4 * 4);
  }
#pragma unroll
  for (int u = 0; u < 8; u++) {
    int idx = tid + u * 256;
    int r = idx >> 5, c4 = idx & 31;
    *(float4*)&Bs[r][c4 * 4] = *(const float4*)(g_tab_inv + (size_t)r * N_T + t0 + c4 * 4);
  }
  __syncthreads();
  float acc[4][8];
#pragma unroll
  for (int i = 0; i < 4; i++)
#pragma unroll
    for (int j = 0; j < 8; j++) acc[i][j] = 0.0f;
#pragma unroll 8
  for (int k = 0; k < 64; k++) {
    float ar[4] = {As[ty * 4 + 0][k], As[ty * 4 + 1][k],
                   As[ty * 4 + 2][k], As[ty * 4 + 3][k]};
    float4 b0 = *(const float4*)&Bs[k][tx * 4];
    float4 b1 = *(const float4*)&Bs[k][tx * 4 + 64];
    float br[8] = {b0.x, b0.y, b0.z, b0.w, b1.x, b1.y, b1.z, b1.w};
#pragma unroll
    for (int i = 0; i < 4; i++)
#pragma unroll
      for (int j = 0; j < 8; j++) acc[i][j] += ar[i] * br[j];
  }
#pragma unroll
  for (int i = 0; i < 4; i++) {
    float* op = out + (size_t)(m0 + ty * 4 + i) * N_T + t0;
    *(float4*)(op + tx * 4)      = make_float4(acc[i][0], acc[i][1], acc[i][2], acc[i][3]);
    *(float4*)(op + tx * 4 + 64) = make_float4(acc[i][4], acc[i][5], acc[i][6], acc[i][7]);
  }
}

// ---------------- launch ----------------
extern "C" void kernel_launch(void* const* d_in, const int* in_sizes, int n_in,
                              void* d_out, int out_size) {
  const float* x     = (const float*)d_in[0];   // (32, 64, 8192)
  const float* w1r   = (const float*)d_in[1];   // (64, 64, 32)
  const float* w1i   = (const float*)d_in[2];   // (64, 64, 32)
  const float* gw    = (const float*)d_in[3];   // (64, 64)
  const float* gamma = (const float*)d_in[4];   // (32,)
  const float* beta  = (const float*)d_in[5];   // (32,)
  float* out = (float*)d_out;                   // (32, 64, 8192)

  k_setup_tables<<<(N_T * N_J + 255) / 256, 256>>>();
  k_setup_cft<<<20, 256>>>();
  k_fwd_dft<<<dim3(N_ROWS / 128, SPLITK), 256>>>(x);
  k_reduce_x<<<(N_ROWS * N_J + 255) / 256, 256>>>();
  k_cft_norm<<<N_ROWS / 8, 256>>>(x, gamma, beta);
  k_gate_mix<<<32, 256>>>(w1r, w1i, gw);
  k_inv_dft<<<dim3(N_T / 128, N_ROWS / 64), 256>>>(out);
}